// round 15
// baseline (speedup 1.0000x reference)
#include <cuda_runtime.h>
#include <cuda_bf16.h>
#include <cstdint>

#define N_NODES 100000
#define N_EDGES 1600000
#define CH 64
#define TCOLS 576               // 9 * 64
#define KDIM 640                // 576 + 64
#define SCAN_B 1024
#define NSCAN_BLOCKS ((N_NODES + SCAN_B - 1) / SCAN_B)   // 98
#define NKC 40                  // K16 steps
#define NFRAG (NKC * 8 * 32)    // 10240 uint4 per layer
#define FM 16                   // nodes per fused block
#define FGRID (N_NODES / FM)    // 6250 (exact)
#define ROWU 80                 // 16B units per smem row (640 bf16)
#define ROWB (ROWU * 16)        // 1280 bytes
#define TILE_BYTES (FM * ROWB)  // 20480 per hi/lo
#define FSMEM (2 * TILE_BYTES)  // 40960 (static here)
#define CONV_BLOCKS ((2 * N_EDGES + 255) / 256)   // 12500
#define WPREP_BLOCKS ((2 * NFRAG + 255) / 256)    // 80

// ------------------------- device scratch (no allocs) -----------------------
__device__ int     g_idx[2 * N_EDGES];
__device__ int     g_cnt[N_NODES];
__device__ int     g_cur[N_NODES];
__device__ int     g_row[N_NODES + 1];
__device__ int     g_bsum[NSCAN_BLOCKS];
__device__ int     g_ready;        // scan rendezvous; reset by scatter for next call
__device__ float4  g_edges[N_EDGES];   // {src(asint), u, v, pad} — 16 B
__device__ float   g_x2[(size_t)N_NODES * CH];
// Fragment-ready split-bf16 weights: [layer][kc][nt][lane] = {bh0,bh1,bl0,bl1}
__device__ uint4   g_wfrag[2][NFRAG];

// ------------------------------ helpers -------------------------------------
__device__ __forceinline__ uint32_t packbf2(float a, float b) {
    __nv_bfloat162 h;
    h.x = __float2bfloat16(a);
    h.y = __float2bfloat16(b);
    return *(uint32_t*)&h;
}

// hi = mantissa truncation of (x,y) packed bf16x2; lo = rn residual.
__device__ __forceinline__ void split2(float x, float y, uint32_t& hi, uint32_t& lo) {
    uint32_t u0 = __float_as_uint(x), u1 = __float_as_uint(y);
    asm("prmt.b32 %0, %1, %2, 0x7632;" : "=r"(hi) : "r"(u0), "r"(u1));
    float l0 = x - __uint_as_float(u0 & 0xFFFF0000u);
    float l1 = y - __uint_as_float(u1 & 0xFFFF0000u);
    asm("cvt.rn.bf16x2.f32 %0, %1, %2;" : "=r"(lo) : "f"(l1), "f"(l0));
}

__device__ __forceinline__ void mma16816(float* c,
    uint32_t a0, uint32_t a1, uint32_t a2, uint32_t a3, uint32_t b0, uint32_t b1)
{
    asm("mma.sync.aligned.m16n8k16.row.col.f32.bf16.bf16.f32 "
        "{%0,%1,%2,%3}, {%4,%5,%6,%7}, {%8,%9}, {%0,%1,%2,%3};"
        : "+f"(c[0]), "+f"(c[1]), "+f"(c[2]), "+f"(c[3])
        : "r"(a0), "r"(a1), "r"(a2), "r"(a3), "r"(b0), "r"(b1));
}

__device__ __forceinline__ void ldsm4(uint32_t* r, uint32_t saddr) {
    asm volatile("ldmatrix.sync.aligned.m8n8.x4.shared.b16 {%0,%1,%2,%3}, [%4];"
                 : "=r"(r[0]), "=r"(r[1]), "=r"(r[2]), "=r"(r[3]) : "r"(saddr));
}

// ---------------------------------------------------------------------------
// Launch 0: convert+histogram (inline dtype detection) + weight-fragment prep.
// ---------------------------------------------------------------------------
__global__ __launch_bounds__(256) void convert_hist_wprep_kernel(
    const int* __restrict__ ei32,
    const float* __restrict__ W1, const float* __restrict__ root1,
    const float* __restrict__ W2, const float* __restrict__ root2)
{
    const int b = blockIdx.x;
    if (b < CONV_BLOCKS) {
        __shared__ int s_is64;
        if (threadIdx.x < 32) {
            int ok = 1;
            for (int i = threadIdx.x * 2 + 1; i < 512; i += 64)
                if (ei32[i] != 0) ok = 0;
            ok = __all_sync(0xffffffffu, ok) ? 1 : 0;
            if (threadIdx.x == 0) s_is64 = ok;
        }
        __syncthreads();
        const int is64 = s_is64;

        int j = b * 256 + threadIdx.x;
        if (j < 2 * N_EDGES) {
            int v = is64 ? ei32[2 * j] : ei32[j];
            v = ((unsigned)v < (unsigned)N_NODES) ? v : 0;
            g_idx[j] = v;
            if (j >= N_EDGES) atomicAdd(&g_cnt[v], 1);
        }
    } else {
        int idx = (b - CONV_BLOCKS) * 256 + threadIdx.x;
        if (idx >= 2 * NFRAG) return;
        const int layer = idx >= NFRAG;
        const int fi = layer ? idx - NFRAG : idx;
        const float* W9   = layer ? W2 : W1;
        const float* root = layer ? root2 : root1;

        int l  = fi & 31;
        int nt = (fi >> 5) & 7;
        int kc = fi >> 8;
        int g = l >> 2, t2 = (l & 3) * 2;
        int n = nt * 8 + g;
        int k0 = kc * 16 + t2;

        float w[4];   // k0, k0+1, k0+8, k0+9
        #pragma unroll
        for (int j2 = 0; j2 < 4; j2++) {
            int kk = k0 + (j2 & 1) + (j2 >> 1) * 8;
            w[j2] = (kk < TCOLS) ? W9[kk * 64 + n] : root[(kk - TCOLS) * 64 + n];
        }
        uint32_t bh0 = packbf2(w[0], w[1]);
        uint32_t bh1 = packbf2(w[2], w[3]);
        __nv_bfloat162* h0 = (__nv_bfloat162*)&bh0;
        __nv_bfloat162* h1 = (__nv_bfloat162*)&bh1;
        uint32_t bl0 = packbf2(w[0] - __bfloat162float(h0->x), w[1] - __bfloat162float(h0->y));
        uint32_t bl1 = packbf2(w[2] - __bfloat162float(h1->x), w[3] - __bfloat162float(h1->y));
        g_wfrag[layer][fi] = make_uint4(bh0, bh1, bl0, bl1);
    }
}

// ---------------------------------------------------------------------------
// Launch 1: single-pass exclusive scan; restores g_cnt/g_cur for next call.
// ---------------------------------------------------------------------------
__global__ __launch_bounds__(SCAN_B) void scan_kernel() {
    __shared__ int s[SCAN_B];
    __shared__ int s_prev;
    const int t = threadIdx.x, b = blockIdx.x;
    const int i = b * SCAN_B + t;
    int v = (i < N_NODES) ? g_cnt[i] : 0;
    s[t] = v;
    __syncthreads();
    for (int off = 1; off < SCAN_B; off <<= 1) {
        int tmp = (t >= off) ? s[t - off] : 0;
        __syncthreads();
        s[t] += tmp;
        __syncthreads();
    }
    if (t == SCAN_B - 1) {
        g_bsum[b] = s[t];
        __threadfence();
        atomicAdd(&g_ready, 1);
    }
    if (t == 0) {
        while (*(volatile int*)&g_ready < NSCAN_BLOCKS) { }
        __threadfence();
        int p = 0;
        for (int q = 0; q < b; q++) p += __ldcg(&g_bsum[q]);
        s_prev = p;
    }
    __syncthreads();
    if (i < N_NODES) {
        g_row[i] = s_prev + s[t] - v;
        g_cnt[i] = 0;
        g_cur[i] = 0;
    }
    if (b == 0 && t == 0) g_row[N_NODES] = N_EDGES;
}

// ---------------------------------------------------------------------------
// Launch 2: dst-sorted scatter of compact {src,u,v} records; resets g_ready.
// ---------------------------------------------------------------------------
__global__ __launch_bounds__(256) void scatter_kernel(const float* __restrict__ pseudo) {
    if (blockIdx.x == 0 && threadIdx.x == 0) g_ready = 0;
    int e = blockIdx.x * 256 + threadIdx.x;
    if (e >= N_EDGES) return;
    int src = g_idx[e];
    int dst = g_idx[N_EDGES + e];
    float2 p = ((const float2*)pseudo)[e];

    int pos = g_row[dst] + atomicAdd(&g_cur[dst], 1);
    g_edges[pos] = make_float4(__int_as_float(src), p.x, p.y, 0.f);
}

// ---------------------------------------------------------------------------
// Launches 3,4: fused layer, FM=16 nodes/block.
//   phase 1: stage X rows (k=576..639) into smem hi/lo
//   phase 2: CSR aggregation, DYNAMIC node scheduling across warps
//   phase 3: 2-way k-split mma (warp = k-half x nt-pair) + smem reduction
// ---------------------------------------------------------------------------
template<bool LAYER2>
__global__ __launch_bounds__(256) void fused_layer_kernel(
    const float* __restrict__ Xext,
    const float* __restrict__ bias,
    float* __restrict__ Hext)
{
    extern __shared__ __align__(128) char smem[];
    char* sHi = smem;
    char* sLo = smem + TILE_BYTES;
    __shared__ int s_task;

    const float* X = LAYER2 ? g_x2 : Xext;
    float* H = LAYER2 ? Hext : g_x2;
    const uint4* wfrag = g_wfrag[LAYER2 ? 1 : 0];

    const int tid = threadIdx.x;
    const int w = tid >> 5, l = tid & 31;
    const int g = l >> 2, t2 = (l & 3) * 2;
    const int mbase = blockIdx.x * FM;

    if (tid == 0) s_task = 0;

    // ---- phase 1: X rows -> cols 576..639 ----
    {
        int r = tid >> 4, cg = tid & 15;         // r 0..15, cg 0..15 (4 cols each)
        const float* xp = X + (size_t)(mbase + r) * CH + cg * 4;
        float4 v0 = *(const float4*)xp;
        uint32_t h0, l0, h1, l1;
        split2(v0.x, v0.y, h0, l0);
        split2(v0.z, v0.w, h1, l1);
        int phys = (72 + (cg >> 1)) ^ (r & 7);
        int off = r * ROWB + phys * 16 + (cg & 1) * 8;
        *(uint2*)(sHi + off) = make_uint2(h0, h1);
        *(uint2*)(sLo + off) = make_uint2(l0, l1);
    }
    __syncthreads();   // s_task visible; phase-1 region disjoint from phase-2 writes

    // ---- phase 2: dynamic node scheduling (16 tasks, 8 warps) ----
    for (;;) {
        int r;
        if (l == 0) r = atomicAdd(&s_task, 1);
        r = __shfl_sync(0xffffffffu, r, 0);
        if (r >= FM) break;

        const int node = mbase + r;
        int beg = g_row[node], end = g_row[node + 1];
        float acc[9][2] = {};

        #pragma unroll 4
        for (int e = beg; e < end; e++) {
            float4 rec = __ldg(&g_edges[e]);
            int src = __float_as_int(rec.x);
            float u = rec.y, v = rec.z;
            float2 xv = __ldg((const float2*)&X[(size_t)src * CH + 2 * l]);

            // basis polynomials (quadratic B-spline), identical to reference
            float bu0 = 0.5f * u * u - u + 0.5f;
            float bu1 = -u * u + u + 0.5f;
            float bu2 = 0.5f * u * u;
            float bv0 = 0.5f * v * v - v + 0.5f;
            float bv1 = -v * v + v + 0.5f;
            float bv2 = 0.5f * v * v;

            // factored: s[a] = bu[a]*x; acc[3a+b] += bv[b]*s[a]
            float sx0 = bu0 * xv.x, sy0 = bu0 * xv.y;
            float sx1 = bu1 * xv.x, sy1 = bu1 * xv.y;
            float sx2 = bu2 * xv.x, sy2 = bu2 * xv.y;
            acc[0][0] += bv0 * sx0; acc[0][1] += bv0 * sy0;
            acc[1][0] += bv1 * sx0; acc[1][1] += bv1 * sy0;
            acc[2][0] += bv2 * sx0; acc[2][1] += bv2 * sy0;
            acc[3][0] += bv0 * sx1; acc[3][1] += bv0 * sy1;
            acc[4][0] += bv1 * sx1; acc[4][1] += bv1 * sy1;
            acc[5][0] += bv2 * sx1; acc[5][1] += bv2 * sy1;
            acc[6][0] += bv0 * sx2; acc[6][1] += bv0 * sy2;
            acc[7][0] += bv1 * sx2; acc[7][1] += bv1 * sy2;
            acc[8][0] += bv2 * sx2; acc[8][1] += bv2 * sy2;
        }

        #pragma unroll
        for (int k = 0; k < 9; k++) {
            uint32_t hi, lo;
            split2(acc[k][0], acc[k][1], hi, lo);
            int phys = (8 * k + (l >> 2)) ^ (r & 7);
            int off = r * ROWB + phys * 16 + (l & 3) * 4;
            *(uint32_t*)(sHi + off) = hi;
            *(uint32_t*)(sLo + off) = lo;
        }
    }
    __syncthreads();

    // ---- phase 3: warp (kh, np): k-range kh*20..+19, n-tiles 2np, 2np+1 ----
    const int kh = w >> 2, np = w & 3;
    const int lm_row = ((l >> 3) & 1) * 8 + (l & 7);
    const int lm_uh = l >> 4;
    const uint32_t sHiB = (uint32_t)__cvta_generic_to_shared(sHi);
    const uint32_t sLoB = (uint32_t)__cvta_generic_to_shared(sLo);

    float acc0[4] = {}, acc1[4] = {};
    #pragma unroll 4
    for (int kq = 0; kq < 20; kq++) {
        int kc = kh * 20 + kq;
        int unit = 2 * kc + lm_uh;
        uint32_t soff = (uint32_t)(lm_row * ROWB + ((unit ^ (lm_row & 7)) << 4));
        uint32_t ah[4], al[4];
        ldsm4(ah, sHiB + soff);
        ldsm4(al, sLoB + soff);

        uint4 bf0 = __ldg(wfrag + (kc * 8 + 2 * np) * 32 + l);
        uint4 bf1 = __ldg(wfrag + (kc * 8 + 2 * np + 1) * 32 + l);
        mma16816(acc0, ah[0], ah[1], ah[2], ah[3], bf0.x, bf0.y);
        mma16816(acc0, ah[0], ah[1], ah[2], ah[3], bf0.z, bf0.w);
        mma16816(acc0, al[0], al[1], al[2], al[3], bf0.x, bf0.y);
        mma16816(acc1, ah[0], ah[1], ah[2], ah[3], bf1.x, bf1.y);
        mma16816(acc1, ah[0], ah[1], ah[2], ah[3], bf1.z, bf1.w);
        mma16816(acc1, al[0], al[1], al[2], al[3], bf1.x, bf1.y);
    }

    // ---- cross-warp reduction: kh=1 partials -> smem -> kh=0 adds ----
    __syncthreads();                       // all ldsm reads of the tile done
    float* rb = (float*)sHi + np * 256 + l;   // 1KB per np, bank-conflict-free
    if (kh == 1) {
        #pragma unroll
        for (int j = 0; j < 4; j++) {
            rb[j * 32] = acc0[j];
            rb[(j + 4) * 32] = acc1[j];
        }
    }
    __syncthreads();
    if (kh == 0) {
        #pragma unroll
        for (int j = 0; j < 4; j++) {
            acc0[j] += rb[j * 32];
            acc1[j] += rb[(j + 4) * 32];
        }

        // ---- epilogue: bias + relu for n-tiles 2np, 2np+1 ----
        const int r0 = mbase + g, r1 = r0 + 8;
        const int c0 = (2 * np) * 8 + t2;
        const int c1 = (2 * np + 1) * 8 + t2;
        float b00 = __ldg(&bias[c0]), b01 = __ldg(&bias[c0 + 1]);
        float b10 = __ldg(&bias[c1]), b11 = __ldg(&bias[c1 + 1]);
        *(float2*)&H[(size_t)r0 * CH + c0] =
            make_float2(fmaxf(acc0[0] + b00, 0.f), fmaxf(acc0[1] + b01, 0.f));
        *(float2*)&H[(size_t)r1 * CH + c0] =
            make_float2(fmaxf(acc0[2] + b00, 0.f), fmaxf(acc0[3] + b01, 0.f));
        *(float2*)&H[(size_t)r0 * CH + c1] =
            make_float2(fmaxf(acc1[0] + b10, 0.f), fmaxf(acc1[1] + b11, 0.f));
        *(float2*)&H[(size_t)r1 * CH + c1] =
            make_float2(fmaxf(acc1[2] + b10, 0.f), fmaxf(acc1[3] + b11, 0.f));
    }
}

// ---------------------------------------------------------------------------
extern "C" void kernel_launch(void* const* d_in, const int* in_sizes, int n_in,
                              void* d_out, int out_size) {
    const float* x      = (const float*)d_in[0];
    const int* ei32     = (const int*)d_in[1];
    const float* pseudo = (const float*)d_in[2];
    const float* W1     = (const float*)d_in[3];
    const float* root1  = (const float*)d_in[4];
    const float* b1     = (const float*)d_in[5];
    const float* W2     = (const float*)d_in[6];
    const float* root2  = (const float*)d_in[7];
    const float* b2     = (const float*)d_in[8];
    float* out          = (float*)d_out;

    cudaFuncSetAttribute(fused_layer_kernel<false>,
                         cudaFuncAttributeMaxDynamicSharedMemorySize, FSMEM);
    cudaFuncSetAttribute(fused_layer_kernel<true>,
                         cudaFuncAttributeMaxDynamicSharedMemorySize, FSMEM);

    // Launch 0: convert + histogram + weight prep
    convert_hist_wprep_kernel<<<CONV_BLOCKS + WPREP_BLOCKS, 256>>>(
        ei32, W1, root1, W2, root2);
    // Launch 1: single-pass scan (restores g_cnt/g_cur)
    scan_kernel<<<NSCAN_BLOCKS, SCAN_B>>>();
    // Launch 2: dst-sorted compact-edge scatter
    scatter_kernel<<<(N_EDGES + 255) / 256, 256>>>(pseudo);
    // Launch 3 (profiled): fused layer 1
    fused_layer_kernel<false><<<FGRID, 256, FSMEM>>>(x, b1, nullptr);
    // Launch 4: fused layer 2
    fused_layer_kernel<true><<<FGRID, 256, FSMEM>>>(nullptr, b2, out);
}

// round 16
// speedup vs baseline: 1.1520x; 1.1520x over previous
#include <cuda_runtime.h>
#include <cuda_bf16.h>
#include <cstdint>

#define N_NODES 100000
#define N_EDGES 1600000
#define CH 64
#define TCOLS 576               // 9 * 64
#define KDIM 640                // 576 + 64
#define SCAN_B 1024
#define NSCAN_BLOCKS ((N_NODES + SCAN_B - 1) / SCAN_B)   // 98
#define NKC 40                  // K16 steps
#define NFRAG (NKC * 8 * 32)    // 10240 uint4 per layer
#define FM 16                   // nodes per fused block
#define FGRID (N_NODES / FM)    // 6250 (exact)
#define ROWU 80                 // 16B units per smem row (640 bf16)
#define ROWB (ROWU * 16)        // 1280 bytes
#define TILE_BYTES (FM * ROWB)  // 20480 per hi/lo
#define FSMEM (2 * TILE_BYTES)  // 40960
#define CONV_BLOCKS ((2 * N_EDGES + 255) / 256)   // 12500
#define WPREP_BLOCKS ((2 * NFRAG + 255) / 256)    // 80

typedef unsigned long long u64;

// ------------------------- device scratch (no allocs) -----------------------
__device__ int     g_idx[2 * N_EDGES];
__device__ int     g_cnt[N_NODES];
__device__ int     g_cur[N_NODES];
__device__ int     g_row[N_NODES + 1];
__device__ int     g_bsum[NSCAN_BLOCKS];
__device__ int     g_ready;        // scan rendezvous; reset by scatter for next call
__device__ float4  g_edges[N_EDGES];   // {src(asint), u, v, pad} — 16 B
__device__ float   g_x2[(size_t)N_NODES * CH];
// Fragment-ready split-bf16 weights: [layer][kc][nt][lane] = {bh0,bh1,bl0,bl1}
__device__ uint4   g_wfrag[2][NFRAG];

// ------------------------------ helpers -------------------------------------
__device__ __forceinline__ uint32_t packbf2(float a, float b) {
    __nv_bfloat162 h;
    h.x = __float2bfloat16(a);
    h.y = __float2bfloat16(b);
    return *(uint32_t*)&h;
}

// hi = mantissa truncation of (x,y) packed bf16x2; lo = rn residual.
__device__ __forceinline__ void split2(float x, float y, uint32_t& hi, uint32_t& lo) {
    uint32_t u0 = __float_as_uint(x), u1 = __float_as_uint(y);
    asm("prmt.b32 %0, %1, %2, 0x7632;" : "=r"(hi) : "r"(u0), "r"(u1));
    float l0 = x - __uint_as_float(u0 & 0xFFFF0000u);
    float l1 = y - __uint_as_float(u1 & 0xFFFF0000u);
    asm("cvt.rn.bf16x2.f32 %0, %1, %2;" : "=r"(lo) : "f"(l1), "f"(l0));
}

// ---- packed f32x2 ops (sm_100) ----
__device__ __forceinline__ u64 pack2(float v) {
    u64 r;
    asm("mov.b64 %0, {%1, %1};" : "=l"(r) : "f"(v));
    return r;
}
__device__ __forceinline__ u64 mul2(u64 a, u64 b) {
    u64 r;
    asm("mul.rn.f32x2 %0, %1, %2;" : "=l"(r) : "l"(a), "l"(b));
    return r;
}
__device__ __forceinline__ u64 fma2p(u64 a, u64 b, u64 c) {
    u64 r;
    asm("fma.rn.f32x2 %0, %1, %2, %3;" : "=l"(r) : "l"(a), "l"(b), "l"(c));
    return r;
}
__device__ __forceinline__ void unpack2(u64 v, float& lo, float& hi) {
    asm("mov.b64 {%0, %1}, %2;" : "=f"(lo), "=f"(hi) : "l"(v));
}

__device__ __forceinline__ void mma16816(float* c,
    uint32_t a0, uint32_t a1, uint32_t a2, uint32_t a3, uint32_t b0, uint32_t b1)
{
    asm("mma.sync.aligned.m16n8k16.row.col.f32.bf16.bf16.f32 "
        "{%0,%1,%2,%3}, {%4,%5,%6,%7}, {%8,%9}, {%0,%1,%2,%3};"
        : "+f"(c[0]), "+f"(c[1]), "+f"(c[2]), "+f"(c[3])
        : "r"(a0), "r"(a1), "r"(a2), "r"(a3), "r"(b0), "r"(b1));
}

__device__ __forceinline__ void ldsm4(uint32_t* r, uint32_t saddr) {
    asm volatile("ldmatrix.sync.aligned.m8n8.x4.shared.b16 {%0,%1,%2,%3}, [%4];"
                 : "=r"(r[0]), "=r"(r[1]), "=r"(r[2]), "=r"(r[3]) : "r"(saddr));
}

// ---------------------------------------------------------------------------
// Launch 0: convert+histogram (inline dtype detection) + weight-fragment prep.
// ---------------------------------------------------------------------------
__global__ __launch_bounds__(256) void convert_hist_wprep_kernel(
    const int* __restrict__ ei32,
    const float* __restrict__ W1, const float* __restrict__ root1,
    const float* __restrict__ W2, const float* __restrict__ root2)
{
    const int b = blockIdx.x;
    if (b < CONV_BLOCKS) {
        __shared__ int s_is64;
        if (threadIdx.x < 32) {
            int ok = 1;
            for (int i = threadIdx.x * 2 + 1; i < 512; i += 64)
                if (ei32[i] != 0) ok = 0;
            ok = __all_sync(0xffffffffu, ok) ? 1 : 0;
            if (threadIdx.x == 0) s_is64 = ok;
        }
        __syncthreads();
        const int is64 = s_is64;

        int j = b * 256 + threadIdx.x;
        if (j < 2 * N_EDGES) {
            int v = is64 ? ei32[2 * j] : ei32[j];
            v = ((unsigned)v < (unsigned)N_NODES) ? v : 0;
            g_idx[j] = v;
            if (j >= N_EDGES) atomicAdd(&g_cnt[v], 1);
        }
    } else {
        int idx = (b - CONV_BLOCKS) * 256 + threadIdx.x;
        if (idx >= 2 * NFRAG) return;
        const int layer = idx >= NFRAG;
        const int fi = layer ? idx - NFRAG : idx;
        const float* W9   = layer ? W2 : W1;
        const float* root = layer ? root2 : root1;

        int l  = fi & 31;
        int nt = (fi >> 5) & 7;
        int kc = fi >> 8;
        int g = l >> 2, t2 = (l & 3) * 2;
        int n = nt * 8 + g;
        int k0 = kc * 16 + t2;

        float w[4];   // k0, k0+1, k0+8, k0+9
        #pragma unroll
        for (int j2 = 0; j2 < 4; j2++) {
            int kk = k0 + (j2 & 1) + (j2 >> 1) * 8;
            w[j2] = (kk < TCOLS) ? W9[kk * 64 + n] : root[(kk - TCOLS) * 64 + n];
        }
        uint32_t bh0 = packbf2(w[0], w[1]);
        uint32_t bh1 = packbf2(w[2], w[3]);
        __nv_bfloat162* h0 = (__nv_bfloat162*)&bh0;
        __nv_bfloat162* h1 = (__nv_bfloat162*)&bh1;
        uint32_t bl0 = packbf2(w[0] - __bfloat162float(h0->x), w[1] - __bfloat162float(h0->y));
        uint32_t bl1 = packbf2(w[2] - __bfloat162float(h1->x), w[3] - __bfloat162float(h1->y));
        g_wfrag[layer][fi] = make_uint4(bh0, bh1, bl0, bl1);
    }
}

// ---------------------------------------------------------------------------
// Launch 1: single-pass exclusive scan; restores g_cnt/g_cur for next call.
// ---------------------------------------------------------------------------
__global__ __launch_bounds__(SCAN_B) void scan_kernel() {
    __shared__ int s[SCAN_B];
    __shared__ int s_prev;
    const int t = threadIdx.x, b = blockIdx.x;
    const int i = b * SCAN_B + t;
    int v = (i < N_NODES) ? g_cnt[i] : 0;
    s[t] = v;
    __syncthreads();
    for (int off = 1; off < SCAN_B; off <<= 1) {
        int tmp = (t >= off) ? s[t - off] : 0;
        __syncthreads();
        s[t] += tmp;
        __syncthreads();
    }
    if (t == SCAN_B - 1) {
        g_bsum[b] = s[t];
        __threadfence();
        atomicAdd(&g_ready, 1);
    }
    if (t == 0) {
        while (*(volatile int*)&g_ready < NSCAN_BLOCKS) { }
        __threadfence();
        int p = 0;
        for (int q = 0; q < b; q++) p += __ldcg(&g_bsum[q]);
        s_prev = p;
    }
    __syncthreads();
    if (i < N_NODES) {
        g_row[i] = s_prev + s[t] - v;
        g_cnt[i] = 0;
        g_cur[i] = 0;
    }
    if (b == 0 && t == 0) g_row[N_NODES] = N_EDGES;
}

// ---------------------------------------------------------------------------
// Launch 2: dst-sorted scatter of compact {src,u,v} records; resets g_ready.
// ---------------------------------------------------------------------------
__global__ __launch_bounds__(256) void scatter_kernel(const float* __restrict__ pseudo) {
    if (blockIdx.x == 0 && threadIdx.x == 0) g_ready = 0;
    int e = blockIdx.x * 256 + threadIdx.x;
    if (e >= N_EDGES) return;
    int src = g_idx[e];
    int dst = g_idx[N_EDGES + e];
    float2 p = ((const float2*)pseudo)[e];

    int pos = g_row[dst] + atomicAdd(&g_cur[dst], 1);
    g_edges[pos] = make_float4(__int_as_float(src), p.x, p.y, 0.f);
}

// ---------------------------------------------------------------------------
// Edge body: packed f32x2 accumulation (lanewise IEEE fp32, same order).
// ---------------------------------------------------------------------------
__device__ __forceinline__ void edge_body(float4 rec, u64 xv2, u64* acc2) {
    float u = rec.y, v = rec.z;
    float bu0 = 0.5f * u * u - u + 0.5f;
    float bu1 = -u * u + u + 0.5f;
    float bu2 = 0.5f * u * u;
    float bv0 = 0.5f * v * v - v + 0.5f;
    float bv1 = -v * v + v + 0.5f;
    float bv2 = 0.5f * v * v;

    u64 s0 = mul2(pack2(bu0), xv2);
    u64 s1 = mul2(pack2(bu1), xv2);
    u64 s2 = mul2(pack2(bu2), xv2);
    u64 pv0 = pack2(bv0), pv1 = pack2(bv1), pv2 = pack2(bv2);
    acc2[0] = fma2p(pv0, s0, acc2[0]);
    acc2[1] = fma2p(pv1, s0, acc2[1]);
    acc2[2] = fma2p(pv2, s0, acc2[2]);
    acc2[3] = fma2p(pv0, s1, acc2[3]);
    acc2[4] = fma2p(pv1, s1, acc2[4]);
    acc2[5] = fma2p(pv2, s1, acc2[5]);
    acc2[6] = fma2p(pv0, s2, acc2[6]);
    acc2[7] = fma2p(pv1, s2, acc2[7]);
    acc2[8] = fma2p(pv2, s2, acc2[8]);
}

__device__ __forceinline__ u64 load_xv(const float* X, float4 rec, int l) {
    u64 xv2;
    const float* p = X + (size_t)__float_as_int(rec.x) * CH + 2 * l;
    asm volatile("ld.global.nc.b64 %0, [%1];" : "=l"(xv2) : "l"(p));
    return xv2;
}

// ---------------------------------------------------------------------------
// Launches 3,4: fused layer, FM=16 nodes/block.
//   phase 1: stage X rows (k=576..639) into smem hi/lo
//   phase 2: static CSR aggregation, 2-edge software pipeline, f32x2 math
//   phase 3: 2-way k-split mma (warp = k-half x nt-pair) + smem reduction
// ---------------------------------------------------------------------------
template<bool LAYER2>
__global__ __launch_bounds__(256) void fused_layer_kernel(
    const float* __restrict__ Xext,
    const float* __restrict__ bias,
    float* __restrict__ Hext)
{
    extern __shared__ __align__(128) char smem[];
    char* sHi = smem;
    char* sLo = smem + TILE_BYTES;

    const float* X = LAYER2 ? g_x2 : Xext;
    float* H = LAYER2 ? Hext : g_x2;
    const uint4* wfrag = g_wfrag[LAYER2 ? 1 : 0];

    const int tid = threadIdx.x;
    const int w = tid >> 5, l = tid & 31;
    const int g = l >> 2, t2 = (l & 3) * 2;
    const int mbase = blockIdx.x * FM;

    // ---- phase 1: X rows -> cols 576..639 ----
    {
        int r = tid >> 4, cg = tid & 15;
        const float* xp = X + (size_t)(mbase + r) * CH + cg * 4;
        float4 v0 = *(const float4*)xp;
        uint32_t h0, l0, h1, l1;
        split2(v0.x, v0.y, h0, l0);
        split2(v0.z, v0.w, h1, l1);
        int phys = (72 + (cg >> 1)) ^ (r & 7);
        int off = r * ROWB + phys * 16 + (cg & 1) * 8;
        *(uint2*)(sHi + off) = make_uint2(h0, h1);
        *(uint2*)(sLo + off) = make_uint2(l0, l1);
    }

    // ---- phase 2: static schedule, warp w -> nodes mbase + w*2 .. +1 ----
    #pragma unroll
    for (int i = 0; i < 2; i++) {
        const int r = w * 2 + i;
        const int node = mbase + r;
        int beg = g_row[node], end = g_row[node + 1];
        u64 acc2[9] = {};

        int e = beg;
        #pragma unroll 2
        for (; e + 1 < end; e += 2) {
            float4 rec0 = __ldg(&g_edges[e]);
            float4 rec1 = __ldg(&g_edges[e + 1]);
            u64 xv0 = load_xv(X, rec0, l);
            u64 xv1 = load_xv(X, rec1, l);
            edge_body(rec0, xv0, acc2);
            edge_body(rec1, xv1, acc2);
        }
        if (e < end) {
            float4 rec0 = __ldg(&g_edges[e]);
            u64 xv0 = load_xv(X, rec0, l);
            edge_body(rec0, xv0, acc2);
        }

        #pragma unroll
        for (int k = 0; k < 9; k++) {
            float ax, ay;
            unpack2(acc2[k], ax, ay);
            uint32_t hi, lo;
            split2(ax, ay, hi, lo);
            int phys = (8 * k + (l >> 2)) ^ (r & 7);
            int off = r * ROWB + phys * 16 + (l & 3) * 4;
            *(uint32_t*)(sHi + off) = hi;
            *(uint32_t*)(sLo + off) = lo;
        }
    }
    __syncthreads();

    // ---- phase 3: warp (kh, np): k-range kh*20..+19, n-tiles 2np, 2np+1 ----
    const int kh = w >> 2, np = w & 3;
    const int lm_row = ((l >> 3) & 1) * 8 + (l & 7);
    const int lm_uh = l >> 4;
    const uint32_t sHiB = (uint32_t)__cvta_generic_to_shared(sHi);
    const uint32_t sLoB = (uint32_t)__cvta_generic_to_shared(sLo);

    float acc0[4] = {}, acc1[4] = {};
    #pragma unroll 4
    for (int kq = 0; kq < 20; kq++) {
        int kc = kh * 20 + kq;
        int unit = 2 * kc + lm_uh;
        uint32_t soff = (uint32_t)(lm_row * ROWB + ((unit ^ (lm_row & 7)) << 4));
        uint32_t ah[4], al[4];
        ldsm4(ah, sHiB + soff);
        ldsm4(al, sLoB + soff);

        uint4 bf0 = __ldg(wfrag + (kc * 8 + 2 * np) * 32 + l);
        uint4 bf1 = __ldg(wfrag + (kc * 8 + 2 * np + 1) * 32 + l);
        mma16816(acc0, ah[0], ah[1], ah[2], ah[3], bf0.x, bf0.y);
        mma16816(acc0, ah[0], ah[1], ah[2], ah[3], bf0.z, bf0.w);
        mma16816(acc0, al[0], al[1], al[2], al[3], bf0.x, bf0.y);
        mma16816(acc1, ah[0], ah[1], ah[2], ah[3], bf1.x, bf1.y);
        mma16816(acc1, ah[0], ah[1], ah[2], ah[3], bf1.z, bf1.w);
        mma16816(acc1, al[0], al[1], al[2], al[3], bf1.x, bf1.y);
    }

    // ---- cross-warp reduction: kh=1 partials -> smem -> kh=0 adds ----
    __syncthreads();                       // all ldsm reads of the tile done
    float* rb = (float*)sHi + np * 256 + l;   // 1KB per np, bank-conflict-free
    if (kh == 1) {
        #pragma unroll
        for (int j = 0; j < 4; j++) {
            rb[j * 32] = acc0[j];
            rb[(j + 4) * 32] = acc1[j];
        }
    }
    __syncthreads();
    if (kh == 0) {
        #pragma unroll
        for (int j = 0; j < 4; j++) {
            acc0[j] += rb[j * 32];
            acc1[j] += rb[(j + 4) * 32];
        }

        // ---- epilogue: bias + relu for n-tiles 2np, 2np+1 ----
        const int r0 = mbase + g, r1 = r0 + 8;
        const int c0 = (2 * np) * 8 + t2;
        const int c1 = (2 * np + 1) * 8 + t2;
        float b00 = __ldg(&bias[c0]), b01 = __ldg(&bias[c0 + 1]);
        float b10 = __ldg(&bias[c1]), b11 = __ldg(&bias[c1 + 1]);
        *(float2*)&H[(size_t)r0 * CH + c0] =
            make_float2(fmaxf(acc0[0] + b00, 0.f), fmaxf(acc0[1] + b01, 0.f));
        *(float2*)&H[(size_t)r1 * CH + c0] =
            make_float2(fmaxf(acc0[2] + b00, 0.f), fmaxf(acc0[3] + b01, 0.f));
        *(float2*)&H[(size_t)r0 * CH + c1] =
            make_float2(fmaxf(acc1[0] + b10, 0.f), fmaxf(acc1[1] + b11, 0.f));
        *(float2*)&H[(size_t)r1 * CH + c1] =
            make_float2(fmaxf(acc1[2] + b10, 0.f), fmaxf(acc1[3] + b11, 0.f));
    }
}

// ---------------------------------------------------------------------------
extern "C" void kernel_launch(void* const* d_in, const int* in_sizes, int n_in,
                              void* d_out, int out_size) {
    const float* x      = (const float*)d_in[0];
    const int* ei32     = (const int*)d_in[1];
    const float* pseudo = (const float*)d_in[2];
    const float* W1     = (const float*)d_in[3];
    const float* root1  = (const float*)d_in[4];
    const float* b1     = (const float*)d_in[5];
    const float* W2     = (const float*)d_in[6];
    const float* root2  = (const float*)d_in[7];
    const float* b2     = (const float*)d_in[8];
    float* out          = (float*)d_out;

    cudaFuncSetAttribute(fused_layer_kernel<false>,
                         cudaFuncAttributeMaxDynamicSharedMemorySize, FSMEM);
    cudaFuncSetAttribute(fused_layer_kernel<true>,
                         cudaFuncAttributeMaxDynamicSharedMemorySize, FSMEM);

    // Launch 0: convert + histogram + weight prep
    convert_hist_wprep_kernel<<<CONV_BLOCKS + WPREP_BLOCKS, 256>>>(
        ei32, W1, root1, W2, root2);
    // Launch 1: single-pass scan (restores g_cnt/g_cur)
    scan_kernel<<<NSCAN_BLOCKS, SCAN_B>>>();
    // Launch 2: dst-sorted compact-edge scatter
    scatter_kernel<<<(N_EDGES + 255) / 256, 256>>>(pseudo);
    // Launch 3 (profiled): fused layer 1
    fused_layer_kernel<false><<<FGRID, 256, FSMEM>>>(x, b1, nullptr);
    // Launch 4: fused layer 2
    fused_layer_kernel<true><<<FGRID, 256, FSMEM>>>(nullptr, b2, out);
}